// round 2
// baseline (speedup 1.0000x reference)
#include <cuda_runtime.h>
#include <math.h>

// FlexibleLogisticModel: f = sigmoid( sum_f w[f] * alpha[ord(f)] * monomial_f(x) )
// over all multiset monomials of degree 0..4 in D=64 vars, in
// combinations_with_replacement lex order. We enumerate combos directly and
// NEVER read the 208MB exponent matrix E. Single fused kernel: last block
// applies sigmoid and resets the accumulator (graph-replay deterministic).
//
// Inputs (metadata order): d_in[0]=x[64] f32, d_in[1]=w[814385] f32,
// d_in[2]=alphas[5] f32, d_in[3]=E (ignored), d_in[4]=ord_ids (ignored).
// Output: 1 float.

#define D 64
#define BASE2 65
#define BASE3 2145
#define BASE4 47905
#define N_TRIPLES 45760   // C(66,3): deg-4 (i1,i2,i3) prefixes
#define N_PAIRS   2080    // C(65,2): deg-3 (i1,i2) prefixes
#define N_UNITS   47905   // 45760 + 2080 + 64 + 1
#define TPB 512
#define NBLK ((N_UNITS + TPB - 1) / TPB)   // 94 -> single wave on 148 SMs

__device__ double   g_acc   = 0.0;
__device__ unsigned g_count = 0;

__device__ __forceinline__ int C2i(int n) { return (n >= 2) ? (n * (n - 1)) / 2 : 0; }
__device__ __forceinline__ int C3i(int n) { return (n >= 3) ? (n * (n - 1) * (n - 2)) / 6 : 0; }
__device__ __forceinline__ int C4i(int n) { return (n >= 4) ? (n * (n - 1) * (n - 2) * (n - 3)) / 24 : 0; }

// Contiguous-run dot: sum_k wp[k] * xp[k], k in [0, len), len <= 64.
// 4 split accumulators + unroll 8 -> 8 outstanding loads, short FMA chains.
__device__ __forceinline__ float run_dot(const float* __restrict__ wp,
                                         const float* __restrict__ xp,
                                         int len)
{
    float s0 = 0.f, s1 = 0.f, s2 = 0.f, s3 = 0.f;
    int k = 0;
    #pragma unroll 2
    for (; k + 8 <= len; k += 8) {
        s0 += wp[k + 0] * xp[k + 0];
        s1 += wp[k + 1] * xp[k + 1];
        s2 += wp[k + 2] * xp[k + 2];
        s3 += wp[k + 3] * xp[k + 3];
        s0 += wp[k + 4] * xp[k + 4];
        s1 += wp[k + 5] * xp[k + 5];
        s2 += wp[k + 6] * xp[k + 6];
        s3 += wp[k + 7] * xp[k + 7];
    }
    for (; k < len; k++) s0 += wp[k] * xp[k];
    return (s0 + s1) + (s2 + s3);
}

__global__ void __launch_bounds__(TPB)
poly_fused_kernel(const float* __restrict__ x,
                  const float* __restrict__ w,
                  const float* __restrict__ alphas,
                  float* __restrict__ out)
{
    __shared__ float xs[D];
    __shared__ float al[5];
    __shared__ double warp_sums[TPB / 32];

    const int tid = threadIdx.x;
    if (tid < D) xs[tid] = x[tid];
    if (tid < 5) al[tid] = alphas[tid];
    __syncthreads();

    const int u = blockIdx.x * TPB + tid;
    double local = 0.0;

    if (u < N_TRIPLES) {
        // ---- degree-4: this thread owns triple-rank t = u; inner dot over i4 ----
        const int t = u;
        int i1 = 0;
        while (i1 < 63 && (N_TRIPLES - C3i(66 - (i1 + 1))) <= t) i1++;
        const int r1 = t - (N_TRIPLES - C3i(66 - i1));
        const int qi1 = C2i(65 - i1);
        int i2 = i1;
        while (i2 < 63 && (qi1 - C2i(65 - (i2 + 1))) <= r1) i2++;
        const int r2 = r1 - (qi1 - C2i(65 - i2));
        const int i3 = i2 + r2;

        const int off = BASE4
                      + (766480 - C4i(67 - i1))
                      + (C3i(66 - i1) - C3i(66 - i2))
                      + (C2i(65 - i2) - C2i(65 - i3));
        const float p = xs[i1] * xs[i2] * xs[i3] * al[4];
        local = (double)(p * run_dot(w + off, xs + i3, D - i3));
    } else if (u < N_TRIPLES + N_PAIRS) {
        // ---- degree-3: this thread owns pair-rank; inner dot over i3 ----
        const int pr = u - N_TRIPLES;
        int i1 = 0;
        while (i1 < 63 && (N_PAIRS - C2i(65 - (i1 + 1))) <= pr) i1++;
        const int i2 = i1 + (pr - (N_PAIRS - C2i(65 - i1)));

        const int off = BASE3
                      + (N_TRIPLES - C3i(66 - i1))
                      + (C2i(65 - i1) - C2i(65 - i2));
        const float p = xs[i1] * xs[i2] * al[3];
        local = (double)(p * run_dot(w + off, xs + i2, D - i2));
    } else if (u < N_TRIPLES + N_PAIRS + D) {
        // ---- degree-2: this thread owns leading index i1; inner dot over i2 ----
        const int i1 = u - (N_TRIPLES + N_PAIRS);
        const int off = BASE2 + (N_PAIRS - C2i(65 - i1));
        const float p = xs[i1] * al[2];
        local = (double)(p * run_dot(w + off, xs + i1, D - i1));
    } else if (u == N_TRIPLES + N_PAIRS + D) {
        // ---- degree 0 and 1 ----
        local = (double)(w[0] * al[0])
              + (double)(al[1] * run_dot(w + 1, xs, D));
    }

    // ---- block reduction (double) ----
    #pragma unroll
    for (int o = 16; o > 0; o >>= 1)
        local += __shfl_down_sync(0xffffffffu, local, o);
    if ((tid & 31) == 0) warp_sums[tid >> 5] = local;
    __syncthreads();

    if (tid == 0) {
        double bs = 0.0;
        #pragma unroll
        for (int i = 0; i < TPB / 32; i++) bs += warp_sums[i];
        atomicAdd(&g_acc, bs);
        __threadfence();
        const unsigned done = atomicAdd(&g_count, 1u);
        if (done == NBLK - 1) {
            // All block contributions are globally visible (fence before count).
            const double a = atomicAdd(&g_acc, 0.0);  // atomic read
            out[0] = (float)(1.0 / (1.0 + exp(-a)));
            g_acc = 0.0;    // reset for next graph replay
            g_count = 0u;
        }
    }
}

extern "C" void kernel_launch(void* const* d_in, const int* in_sizes, int n_in,
                              void* d_out, int out_size)
{
    const float* x      = (const float*)d_in[0];
    const float* w      = (const float*)d_in[1];
    const float* alphas = (const float*)d_in[2];
    // d_in[3] = E (constant exponents, NOT read), d_in[4] = ord_ids (NOT read)
    float* out = (float*)d_out;

    poly_fused_kernel<<<NBLK, TPB>>>(x, w, alphas, out);
}

// round 3
// speedup vs baseline: 1.4135x; 1.4135x over previous
#include <cuda_runtime.h>
#include <math.h>

// FlexibleLogisticModel: f = sigmoid( sum_f w[f] * alpha[ord(f)] * monomial_f(x) )
// over all multiset monomials of degree 0..4 in D=64 vars, lex (CWR) order.
// We enumerate combos directly (w's deg-m sections are contiguous runs) and
// never read the 208MB exponent matrix. Unranking uses closed-form cbrt/sqrt
// inversion of binomials + small fixup. Single fused kernel; last block applies
// sigmoid and resets accumulators (graph-replay deterministic).

#define D 64
#define BASE2 65
#define BASE3 2145
#define BASE4 47905
#define N_TRIPLES 45760   // C(66,3): deg-4 (i1,i2,i3) prefixes
#define N_PAIRS   2080    // C(65,2): deg-3 (i1,i2) prefixes
#define N_UNITS   47905   // 45760 + 2080 + 64 + 1
#define TPB 256
#define NBLK ((N_UNITS + TPB - 1) / TPB)   // 188 -> 1.27 waves on 148 SMs

__device__ double   g_acc   = 0.0;
__device__ unsigned g_count = 0;

__device__ __forceinline__ int C2i(int n) { return (n >= 2) ? (n * (n - 1)) / 2 : 0; }
__device__ __forceinline__ int C3i(int n) { return (n >= 3) ? (n * (n - 1) * (n - 2)) / 6 : 0; }
__device__ __forceinline__ int C4i(int n) { return (n >= 4) ? (n * (n - 1) * (n - 2) * (n - 3)) / 24 : 0; }

// smallest n >= 3 with C3(n) >= v   (v in [1, 45760])
__device__ __forceinline__ int inv_C3(int v) {
    int n = (int)cbrtf(6.0f * (float)v);   // C3(n) ~ n^3/6
    n = (n > 3) ? n - 2 : 3;               // start safely below
    while (C3i(n) < v) n++;                // <=4 steps
    return n;
}

// smallest n >= 2 with C2(n) >= v   (v in [1, 2080])
__device__ __forceinline__ int inv_C2(int v) {
    int n = (int)(0.5f * (1.0f + sqrtf(8.0f * (float)v + 1.0f)));
    n = (n > 2) ? n - 1 : 2;
    while (C2i(n) < v) n++;                // <=3 steps
    return n;
}

__global__ void __launch_bounds__(TPB)
poly_fused_kernel(const float* __restrict__ x,
                  const float* __restrict__ w,
                  const float* __restrict__ alphas,
                  float* __restrict__ out)
{
    __shared__ float xs[D];
    __shared__ float al[5];
    __shared__ double warp_sums[TPB / 32];

    const int tid = threadIdx.x;
    if (tid < D) xs[tid] = x[tid];
    if (tid < 5) al[tid] = alphas[tid];
    __syncthreads();

    const int u = blockIdx.x * TPB + tid;
    double local = 0.0;

    if (u < N_TRIPLES) {
        // ---- degree-4: unrank triple t = u, inner dot over i4 ----
        const int t = u;
        const int rem3 = N_TRIPLES - t;            // in [1, 45760]
        const int a = inv_C3(rem3);                // a = 66 - i1
        const int i1 = 66 - a;
        const int r1 = C3i(a) - rem3;              // rank within i1's block
        const int rem2 = C2i(65 - i1) - r1;        // in [1, C2(65-i1)]
        const int b = inv_C2(rem2);                // b = 65 - i2
        const int i2 = 65 - b;
        const int r2 = C2i(b) - rem2;
        const int i3 = i2 + r2;

        const int off = BASE4
                      + (766480 - C4i(67 - i1))
                      + (C3i(66 - i1) - C3i(66 - i2))
                      + (C2i(65 - i2) - C2i(65 - i3));
        const float p = xs[i1] * xs[i2] * xs[i3] * al[4];
        float s = 0.0f;
        #pragma unroll 4
        for (int i4 = i3; i4 < D; i4++)
            s += w[off + (i4 - i3)] * xs[i4];
        local = (double)(p * s);
    } else if (u < N_TRIPLES + N_PAIRS) {
        // ---- degree-3: unrank pair, inner dot over i3 ----
        const int pr = u - N_TRIPLES;
        const int rem2 = N_PAIRS - pr;             // in [1, 2080]
        const int n = inv_C2(rem2);                // n = 65 - i1
        const int i1 = 65 - n;
        const int r = C2i(n) - rem2;
        const int i2 = i1 + r;

        const int off = BASE3
                      + (N_TRIPLES - C3i(66 - i1))
                      + (C2i(65 - i1) - C2i(65 - i2));
        const float p = xs[i1] * xs[i2] * al[3];
        float s = 0.0f;
        #pragma unroll 4
        for (int i3 = i2; i3 < D; i3++)
            s += w[off + (i3 - i2)] * xs[i3];
        local = (double)(p * s);
    } else if (u < N_TRIPLES + N_PAIRS + D) {
        // ---- degree-2: leading index i1, inner dot over i2 ----
        const int i1 = u - (N_TRIPLES + N_PAIRS);
        const int off = BASE2 + (N_PAIRS - C2i(65 - i1));
        const float p = xs[i1] * al[2];
        float s = 0.0f;
        #pragma unroll 4
        for (int i2 = i1; i2 < D; i2++)
            s += w[off + (i2 - i1)] * xs[i2];
        local = (double)(p * s);
    } else if (u == N_TRIPLES + N_PAIRS + D) {
        // ---- degree 0 and 1 ----
        double s = (double)(w[0] * al[0]);
        float s1 = 0.0f;
        #pragma unroll 4
        for (int i = 0; i < D; i++)
            s1 += w[1 + i] * xs[i];
        local = s + (double)(al[1] * s1);
    }

    // ---- block reduction (double) ----
    #pragma unroll
    for (int o = 16; o > 0; o >>= 1)
        local += __shfl_down_sync(0xffffffffu, local, o);
    if ((tid & 31) == 0) warp_sums[tid >> 5] = local;
    __syncthreads();

    if (tid == 0) {
        double bs = 0.0;
        #pragma unroll
        for (int i = 0; i < TPB / 32; i++) bs += warp_sums[i];
        atomicAdd(&g_acc, bs);
        __threadfence();
        const unsigned done = atomicAdd(&g_count, 1u);
        if (done == NBLK - 1) {
            const double a = atomicAdd(&g_acc, 0.0);  // atomic read, all blocks visible
            out[0] = (float)(1.0 / (1.0 + exp(-a)));
            g_acc = 0.0;    // reset for next graph replay
            g_count = 0u;
        }
    }
}

extern "C" void kernel_launch(void* const* d_in, const int* in_sizes, int n_in,
                              void* d_out, int out_size)
{
    const float* x      = (const float*)d_in[0];
    const float* w      = (const float*)d_in[1];
    const float* alphas = (const float*)d_in[2];
    // d_in[3] = E (constant exponents, NOT read), d_in[4] = ord_ids (NOT read)
    float* out = (float*)d_out;

    poly_fused_kernel<<<NBLK, TPB>>>(x, w, alphas, out);
}

// round 4
// speedup vs baseline: 1.7552x; 1.2418x over previous
#include <cuda_runtime.h>
#include <math.h>

// FlexibleLogisticModel: f = sigmoid( sum_f w[f] * alpha[ord(f)] * monomial_f(x) )
// over all multiset monomials of degree 0..4 in D=64 vars, lex (CWR) order.
// Combos are enumerated directly (never reads the 208MB exponent matrix).
//
// Schedule: work is grouped so every warp has a UNIFORM inner-run length:
//   deg-4: warps grouped by i3 (run len 64-i3), lanes = triples (i1<=i2<=i3)
//   deg-3: warps grouped by i2 (run len 64-i2), lanes = i1
//   deg-2: 2 warps, lane = i1;  deg-0/1: 1 lane.
// Inner dot uses 16-wide load batches (MLP=16) + 4 split accumulators.
// Single fused kernel: last block applies sigmoid and resets accumulators.

#define D 64
#define BASE2 65
#define BASE3 2145
#define BASE4 47905
#define N_TRIPLES 45760   // C(66,3)
#define N_PAIRS   2080    // C(65,2)
#define TPB 128           // 4 warps / block

__device__ double   g_acc   = 0.0;
__device__ unsigned g_count = 0;

__device__ __host__ __forceinline__ int C2i(int n) { return (n >= 2) ? (n * (n - 1)) / 2 : 0; }
__device__ __host__ __forceinline__ int C3i(int n) { return (n >= 3) ? (n * (n - 1) * (n - 2)) / 6 : 0; }
__device__ __host__ __forceinline__ int C4i(int n) { return (n >= 4) ? (n * (n - 1) * (n - 2) * (n - 3)) / 24 : 0; }
__device__ __forceinline__ int T2(int k) { return (k * (k + 1)) / 2; }

// Uniform-length contiguous dot: sum_k wp[k]*xp[k], len in [1,64].
// 16 loads issued per batch -> at most 4 L2 round trips for len=64.
__device__ __forceinline__ float dotrun(const float* __restrict__ wp,
                                        const float* __restrict__ xp, int len)
{
    float s0 = 0.f, s1 = 0.f, s2 = 0.f, s3 = 0.f;
    int k = 0;
    for (; k + 16 <= len; k += 16) {
        float a0 = wp[k+0],  a1 = wp[k+1],  a2 = wp[k+2],  a3 = wp[k+3];
        float a4 = wp[k+4],  a5 = wp[k+5],  a6 = wp[k+6],  a7 = wp[k+7];
        float a8 = wp[k+8],  a9 = wp[k+9],  a10 = wp[k+10], a11 = wp[k+11];
        float a12 = wp[k+12], a13 = wp[k+13], a14 = wp[k+14], a15 = wp[k+15];
        s0 += a0 * xp[k+0];   s1 += a1 * xp[k+1];
        s2 += a2 * xp[k+2];   s3 += a3 * xp[k+3];
        s0 += a4 * xp[k+4];   s1 += a5 * xp[k+5];
        s2 += a6 * xp[k+6];   s3 += a7 * xp[k+7];
        s0 += a8 * xp[k+8];   s1 += a9 * xp[k+9];
        s2 += a10 * xp[k+10]; s3 += a11 * xp[k+11];
        s0 += a12 * xp[k+12]; s1 += a13 * xp[k+13];
        s2 += a14 * xp[k+14]; s3 += a15 * xp[k+15];
    }
    for (; k + 4 <= len; k += 4) {
        float a0 = wp[k], a1 = wp[k+1], a2 = wp[k+2], a3 = wp[k+3];
        s0 += a0 * xp[k];   s1 += a1 * xp[k+1];
        s2 += a2 * xp[k+2]; s3 += a3 * xp[k+3];
    }
    for (; k < len; ++k) s0 += wp[k] * xp[k];
    return (s0 + s1) + (s2 + s3);
}

__global__ void __launch_bounds__(TPB)
poly_fused_kernel(const float* __restrict__ x,
                  const float* __restrict__ w,
                  const float* __restrict__ alphas,
                  float* __restrict__ out)
{
    __shared__ float xs[D];
    __shared__ float al[5];
    __shared__ int   cum4[65];   // exclusive prefix of warps-per-i3-group
    __shared__ int   w0sum;
    __shared__ double warp_sums[TPB / 32];

    const int tid  = threadIdx.x;
    const int lane = tid & 31;
    if (tid < D) xs[tid] = x[tid];
    if (tid < 5) al[tid] = alphas[tid];

    // Build cum4[] with two warp shfl-scans (threads 0..63 own entries).
    int cnt = 0;
    if (tid < D) cnt = (((tid + 1) * (tid + 2)) / 2 + 31) / 32;  // warps in i3-group tid
    int v = cnt;
    #pragma unroll
    for (int o = 1; o < 32; o <<= 1) {
        int nbr = __shfl_up_sync(0xffffffffu, v, o);
        if (lane >= o) v += nbr;
    }
    if (tid == 31) w0sum = v;
    __syncthreads();
    if (tid >= 32 && tid < D) v += w0sum;
    if (tid < D) cum4[tid] = v - cnt;      // exclusive prefix
    if (tid == D - 1) cum4[D] = v;         // total deg-4 warps (W4)
    __syncthreads();

    const int W4 = cum4[D];
    const int gw = (blockIdx.x * TPB + tid) >> 5;  // global warp id
    double local = 0.0;

    if (gw < W4) {
        // ---- degree-4: find i3 group (binary search, warp-uniform) ----
        int lo = 0, hi = D - 1;
        #pragma unroll
        for (int it = 0; it < 6; ++it) {
            int mid = (lo + hi + 1) >> 1;
            if (cum4[mid] <= gw) lo = mid; else hi = mid - 1;
        }
        const int i3 = lo;
        const int tr = (gw - cum4[i3]) * 32 + lane;      // triple rank within group
        const int Ti = ((i3 + 1) * (i3 + 2)) / 2;
        if (tr < Ti) {
            // triangular unrank: i2 = largest k with T2(k) <= tr, i1 = tr - T2(i2)
            int i2 = (int)(0.5f * (sqrtf(8.0f * (float)tr + 1.0f) - 1.0f));
            while (T2(i2 + 1) <= tr) i2++;
            while (T2(i2) > tr) i2--;
            const int i1 = tr - T2(i2);

            const int off = BASE4
                          + (766480 - C4i(67 - i1))
                          + (C3i(66 - i1) - C3i(66 - i2))
                          + (C2i(65 - i2) - C2i(65 - i3));
            const float p = xs[i1] * xs[i2] * xs[i3] * al[4];
            local = (double)(p * dotrun(w + off, xs + i3, D - i3));
        }
    } else if (gw < W4 + 96) {
        // ---- degree-3: group by i2 (96 warps), lane covers i1 ----
        const int h = gw - W4;
        int i1, i2;
        if (h < 32) { i2 = h; i1 = lane; }
        else        { int q = h - 32; i2 = 32 + (q >> 1); i1 = ((q & 1) << 5) + lane; }
        if (i1 <= i2) {
            const int off = BASE3
                          + (N_TRIPLES - C3i(66 - i1))
                          + (C2i(65 - i1) - C2i(65 - i2));
            const float p = xs[i1] * xs[i2] * al[3];
            local = (double)(p * dotrun(w + off, xs + i2, D - i2));
        }
    } else if (gw < W4 + 98) {
        // ---- degree-2: 2 warps, lane = i1 ----
        const int i1 = ((gw - W4 - 96) << 5) + lane;
        const int off = BASE2 + (N_PAIRS - C2i(65 - i1));
        const float p = xs[i1] * al[2];
        local = (double)(p * dotrun(w + off, xs + i1, D - i1));
    } else if (gw == W4 + 98 && lane == 0) {
        // ---- degree 0 and 1 ----
        local = (double)(w[0] * al[0])
              + (double)(al[1] * dotrun(w + 1, xs, D));
    }

    // ---- block reduction (double) ----
    #pragma unroll
    for (int o = 16; o > 0; o >>= 1)
        local += __shfl_down_sync(0xffffffffu, local, o);
    if (lane == 0) warp_sums[tid >> 5] = local;
    __syncthreads();

    if (tid == 0) {
        double bs = 0.0;
        #pragma unroll
        for (int i = 0; i < TPB / 32; i++) bs += warp_sums[i];
        atomicAdd(&g_acc, bs);
        __threadfence();
        const unsigned done = atomicAdd(&g_count, 1u);
        if (done == gridDim.x - 1) {
            const double a = atomicAdd(&g_acc, 0.0);  // atomic read, all contributions visible
            out[0] = (float)(1.0 / (1.0 + exp(-a)));
            g_acc = 0.0;    // reset for next graph replay
            g_count = 0u;
        }
    }
}

extern "C" void kernel_launch(void* const* d_in, const int* in_sizes, int n_in,
                              void* d_out, int out_size)
{
    const float* x      = (const float*)d_in[0];
    const float* w      = (const float*)d_in[1];
    const float* alphas = (const float*)d_in[2];
    // d_in[3] = E (constant exponents, NOT read), d_in[4] = ord_ids (NOT read)
    float* out = (float*)d_out;

    // Host-side mirror of the warp schedule size (deterministic, cheap).
    int W4 = 0;
    for (int i3 = 0; i3 < D; ++i3)
        W4 += (((i3 + 1) * (i3 + 2)) / 2 + 31) / 32;   // = 1461
    const int total_warps = W4 + 96 + 2 + 1;           // deg3 + deg2 + deg01
    const int nblk = (total_warps + (TPB / 32) - 1) / (TPB / 32);

    poly_fused_kernel<<<nblk, TPB>>>(x, w, alphas, out);
}